// round 13
// baseline (speedup 1.0000x reference)
#include <cuda_runtime.h>

#define BB 2
#define NN 16384
#define MM 4096
#define CC 32
#define KK 32

// float(0.01) — comparison threshold, frozen (bit-matches reference)
#define R2 0.00999999977648258209228515625f

// Anisotropic grid: 10 x 10 x 100 (z scanned as contiguous runs -> fine z is free)
#define GDXY 10
#define GDZ 100
#define NC 10000
#define CAP 256

// Scratch. g_cellcur is zero at module load and restored to zero by
// group_kernel at the end of every kernel_launch call.
__device__ int    g_idx[BB * MM * KK];        // ball-query result [B][M][K]
__device__ float  g_feat_t[BB * NN * CC];     // transposed features [B][N][C]
__device__ float4 g_pts4[BB * NN];            // cell-sorted (x,y,z,idx-bits)
__device__ float  g_p2s[BB * NN];             // cell-sorted p2 (frozen rounding)
__device__ int    g_cellcur[BB * NC];         // counts -> scatter cursors
__device__ int    g_cellstart[BB * (NC + 1)];

// ---------------------------------------------------------------------------
__device__ __forceinline__ int cell_of(float x, float y, float z) {
    int cx = (int)(x * 10.f);  cx = cx < 0 ? 0 : (cx > 9 ? 9 : cx);
    int cy = (int)(y * 10.f);  cy = cy < 0 ? 0 : (cy > 9 ? 9 : cy);
    int cz = (int)(z * 100.f); cz = cz < 0 ? 0 : (cz > 99 ? 99 : cz);
    return (cx * GDXY + cy) * GDZ + cz;
}

// ---------------------------------------------------------------------------
// Fused count + feature transpose. Blocks [0,128): histogram points into
// cells (global atomics). Blocks [128,1152): transpose feat [B][C][N] ->
// [B][N][C] in 32x32 tiles (hides the count blocks' atomic latency).
// ---------------------------------------------------------------------------
__global__ __launch_bounds__(256) void count_transpose_kernel(
    const float* __restrict__ pts,    // [B][3][N]
    const float* __restrict__ feat)   // [B][C][N]
{
    if (blockIdx.x < (BB * NN) / 256) {
        const int i = blockIdx.x * 256 + threadIdx.x;
        const int b = i >> 14;                    // / NN
        const int n = i & (NN - 1);
        const float* __restrict__ P = pts + b * 3 * NN;
        atomicAdd(&g_cellcur[b * NC + cell_of(P[n], P[NN + n], P[2 * NN + n])], 1);
    } else {
        __shared__ float sm[32][33];
        const int t  = blockIdx.x - (BB * NN) / 256;   // 0..1023
        const int b  = t >> 9;
        const int n0 = (t & 511) * 32;
        const int tx = threadIdx.x & 31;
        const int ty = threadIdx.x >> 5;               // 0..7

        #pragma unroll
        for (int i = ty; i < 32; i += 8)
            sm[i][tx] = feat[(b * CC + i) * NN + n0 + tx];
        __syncthreads();
        #pragma unroll
        for (int i = ty; i < 32; i += 8)
            g_feat_t[(size_t)(b * NN + n0 + i) * CC + tx] = sm[tx][i];
    }
}

// grid = BB blocks, 1024 threads: exclusive scan of 10000 counts per batch.
// Thread t owns elements [t*10, t*10+10): local scan + block Hillis-Steele.
__global__ __launch_bounds__(1024) void prefix_kernel() {
    __shared__ int s[1024];
    const int b = blockIdx.x, tid = threadIdx.x;

    int loc[10];
    int sum = 0;
    #pragma unroll
    for (int k = 0; k < 10; ++k) {
        const int ci = tid * 10 + k;
        const int v = (ci < NC) ? g_cellcur[b * NC + ci] : 0;
        loc[k] = sum;                  // local exclusive prefix
        sum += v;
    }
    s[tid] = sum;
    __syncthreads();
    #pragma unroll
    for (int off = 1; off < 1024; off <<= 1) {
        const int t = (tid >= off) ? s[tid - off] : 0;
        __syncthreads();
        s[tid] += t;
        __syncthreads();
    }
    const int base = s[tid] - sum;     // exclusive block offset
    #pragma unroll
    for (int k = 0; k < 10; ++k) {
        const int ci = tid * 10 + k;
        if (ci < NC) {
            const int excl = base + loc[k];
            g_cellstart[b * (NC + 1) + ci] = excl;
            g_cellcur[b * NC + ci] = excl;       // scatter cursor
        }
    }
    if (tid == 1023) g_cellstart[b * (NC + 1) + NC] = s[tid];   // = NN
}

// 2 points per thread, loads batched upfront. Also stores precomputed p2
// (frozen rounding: (x*x + y*y) + z*z, plain mul/add) beside each point.
__global__ __launch_bounds__(256) void scatter_kernel(const float* __restrict__ pts) {
    const int i0 = (blockIdx.x * 256 + threadIdx.x) * 2;
    const int b  = i0 >> 14;                     // pairs never straddle batches
    const int n0 = i0 & (NN - 1);
    const float* __restrict__ P = pts + b * 3 * NN;

    float x[2], y[2], z[2];
    #pragma unroll
    for (int j = 0; j < 2; ++j) {
        x[j] = __ldg(P + n0 + j);
        y[j] = __ldg(P + NN + n0 + j);
        z[j] = __ldg(P + 2 * NN + n0 + j);
    }
    #pragma unroll
    for (int j = 0; j < 2; ++j) {
        const int pos = atomicAdd(&g_cellcur[b * NC + cell_of(x[j], y[j], z[j])], 1);
        g_pts4[b * NN + pos] = make_float4(x[j], y[j], z[j], __int_as_float(n0 + j));
        g_p2s[b * NN + pos] = __fadd_rn(
            __fadd_rn(__fmul_rn(x[j], x[j]), __fmul_rn(y[j], y[j])),
            __fmul_rn(z[j], z[j]));
    }
}

// ---------------------------------------------------------------------------
// Query: warp per center. Scan the xy-neighborhood as contiguous fine-z runs
// of the cell-sorted array (z-window 0.21 vs 0.30 -> ~30% fewer candidates);
// p2 preloaded; collect valid ORIGINAL indices, rank-select 32 smallest via
// int4 smem broadcasts (4 candidates per LDS.128).
// Arithmetic bit-matches XLA lowering (FROZEN):
//   p2,c2: (x*x + y*y) + z*z  plain mul/add   (p2 precomputed at scatter)
//   dot:   fma(cz,pz, fma(cy,py, cx*px))
//   d2:    (c2 + p2) - 2*dot
// ---------------------------------------------------------------------------
#define QW 8
__global__ __launch_bounds__(256) void query_kernel(const float* __restrict__ ctr)
{
    __shared__ int4 buf4[QW][CAP / 4];
    __shared__ int  sidx[QW][KK];

    const int w = threadIdx.x >> 5;
    const int lane = threadIdx.x & 31;
    const int gw = blockIdx.x * QW + w;           // 1024 blocks * 8 warps
    const int b = gw >> 12;                       // / MM
    const int m = gw & (MM - 1);
    int* __restrict__ bufw = reinterpret_cast<int*>(buf4[w]);

    const float cx = ctr[(b * 3 + 0) * MM + m];
    const float cy = ctr[(b * 3 + 1) * MM + m];
    const float cz = ctr[(b * 3 + 2) * MM + m];
    const float c2 = __fadd_rn(__fadd_rn(__fmul_rn(cx, cx), __fmul_rn(cy, cy)),
                               __fmul_rn(cz, cz));

    // conservative cell ranges (1e-4 margin swamps fp rounding)
    int lox = (int)((cx - 0.1001f) * 10.f);  lox = lox < 0 ? 0 : lox;
    int hix = (int)((cx + 0.1001f) * 10.f);  hix = hix > 9 ? 9 : hix;
    int loy = (int)((cy - 0.1001f) * 10.f);  loy = loy < 0 ? 0 : loy;
    int hiy = (int)((cy + 0.1001f) * 10.f);  hiy = hiy > 9 ? 9 : hiy;
    int loz = (int)((cz - 0.1001f) * 100.f); loz = loz < 0 ? 0 : loz;
    int hiz = (int)((cz + 0.1001f) * 100.f); hiz = hiz > 99 ? 99 : hiz;

    const int* __restrict__ cs = g_cellstart + b * (NC + 1);
    const float4* __restrict__ pp = g_pts4 + b * NN;
    const float* __restrict__ sp2 = g_p2s + b * NN;

    int cnt = 0;
    for (int xi = lox; xi <= hix; ++xi) {
        for (int yi = loy; yi <= hiy; ++yi) {
            const int base = (xi * GDXY + yi) * GDZ;
            const int s = cs[base + loz];
            const int e = cs[base + hiz + 1];
            for (int t = s + lane; t - lane < e; t += 32) {
                const bool inb = t < e;
                float4 q = make_float4(0.f, 0.f, 0.f, 0.f);
                float p2 = 0.f;
                if (inb) { q = pp[t]; p2 = sp2[t]; }
                const float dot = __fmaf_rn(cz, q.z, __fmaf_rn(cy, q.y, __fmul_rn(cx, q.x)));
                const float d2 = __fadd_rn(__fadd_rn(c2, p2), __fmul_rn(-2.0f, dot));
                const bool valid = inb && (d2 < R2);
                const unsigned mask = __ballot_sync(0xffffffffu, valid);
                if (valid) {
                    const int pos = cnt + __popc(mask & ((1u << lane) - 1u));
                    if (pos < CAP) bufw[pos] = __float_as_int(q.w);
                }
                cnt += __popc(mask);
            }
        }
    }
    __syncwarp();

    // Pad to int4 boundary with IMAX so the vectorized rank loop reads no stale data.
    const int cc = cnt < CAP ? cnt : CAP;
    const int IMAX = 0x7fffffff;
    if (lane < 3) {
        const int pi = cc + lane;
        if (pi < CAP) bufw[pi] = IMAX;
    }
    // Read targets (slots < cc only; pad writes are at >= cc -> no race)
    const int v0 = (lane      < cc) ? bufw[lane]      : IMAX;
    const int v1 = (lane + 32 < cc) ? bufw[lane + 32] : IMAX;
    const int v2 = (lane + 64 < cc) ? bufw[lane + 64] : IMAX;
    const int v3 = (lane + 96 < cc) ? bufw[lane + 96] : IMAX;
    __syncwarp();

    // Rank via int4 broadcasts: 4 candidates per LDS.128. IMAX pads never
    // rank below a real value (indices < 16384), so ranks are exact.
    int r0 = 0, r1 = 0, r2 = 0, r3 = 0;
    const int n4 = (cc + 3) >> 2;
    for (int g = 0; g < n4; ++g) {
        const int4 u = buf4[w][g];
        r0 += (u.x < v0) + (u.y < v0) + (u.z < v0) + (u.w < v0);
        r1 += (u.x < v1) + (u.y < v1) + (u.z < v1) + (u.w < v1);
        r2 += (u.x < v2) + (u.y < v2) + (u.z < v2) + (u.w < v2);
        r3 += (u.x < v3) + (u.y < v3) + (u.z < v3) + (u.w < v3);
    }
    if (lane      < cc && r0 < KK) sidx[w][r0] = v0;
    if (lane + 32 < cc && r1 < KK) sidx[w][r1] = v1;
    if (lane + 64 < cc && r2 < KK) sidx[w][r2] = v2;
    if (lane + 96 < cc && r3 < KK) sidx[w][r3] = v3;
    // rare overflow path (cc in (128,256])
    for (int j = 128 + lane; j < cc; j += 32) {
        const int vv = bufw[j];
        int r = 0;
        for (int g = 0; g < cc; ++g) r += (bufw[g] < vv);
        if (r < KK) sidx[w][r] = vv;
    }
    __syncwarp();

    int outv;
    if (cnt == 0) {
        outv = 0;
    } else {
        const int first = sidx[w][0];
        outv = (lane < cnt) ? sidx[w][lane] : first;
    }
    g_idx[(b * MM + m) * KK + lane] = outv;
}

// ---------------------------------------------------------------------------
// Unified grouping: grid (M/32, 5, B), 256 threads.
// y in [0,4): feature plane kc=y — warp w owns k=kc*8+w; MLP-batched 128B row
//             gathers from g_feat_t staged through a padded smem tile.
// y == 4   : coords — warp w owns k in [4w, 4w+4); per-lane m; scattered 4B
//            gathers, coalesced-over-m stores. These blocks also restore
//            g_cellcur to zero for the next call (disjoint contiguous ranges).
// ---------------------------------------------------------------------------
__global__ __launch_bounds__(256) void group_kernel(
    const float* __restrict__ pts,    // [B][3][N]
    const float* __restrict__ ctr,    // [B][3][M]
    float* __restrict__ out)          // [B][35][K][M]
{
    const int tid  = threadIdx.x;
    const int w    = tid >> 5;
    const int lane = tid & 31;
    const int m0 = blockIdx.x * 32;
    const int b  = blockIdx.z;

    if (blockIdx.y < 4) {
        __shared__ int   sidx2[32 * 8];          // [m][kk]
        __shared__ float tile[32 * 257];         // [c][w*32+m], padded
        const int kc = blockIdx.y;

        {
            const int ml = tid >> 3, kk = tid & 7;
            sidx2[ml * 8 + kk] = g_idx[(b * MM + m0 + ml) * KK + kc * 8 + kk];
        }
        __syncthreads();

        const float* __restrict__ ft = g_feat_t + (size_t)b * NN * CC + lane;

        int idxs[32];
        #pragma unroll
        for (int m = 0; m < 32; ++m) idxs[m] = sidx2[m * 8 + w];

        #pragma unroll
        for (int mb = 0; mb < 4; ++mb) {
            float v[8];
            #pragma unroll
            for (int j = 0; j < 8; ++j)
                v[j] = __ldg(ft + (size_t)idxs[mb * 8 + j] * CC);
            #pragma unroll
            for (int j = 0; j < 8; ++j)
                tile[lane * 257 + w * 32 + mb * 8 + j] = v[j];
        }
        __syncthreads();

        #pragma unroll
        for (int i = 0; i < 32; ++i) {
            out[(size_t)((b * 35 + 3 + i) * KK + kc * 8 + w) * MM + m0 + lane] =
                tile[i * 257 + w * 32 + lane];
        }
    } else {
        __shared__ int sidxc[32 * 33];           // [m][k] padded

        for (int t = tid; t < 32 * KK; t += 256) {
            const int ml = t >> 5, k = t & 31;
            sidxc[ml * 33 + k] = g_idx[(b * MM + m0 + ml) * KK + k];
        }
        __syncthreads();

        int idx4[4];
        #pragma unroll
        for (int j = 0; j < 4; ++j) idx4[j] = sidxc[lane * 33 + w * 4 + j];

        #pragma unroll
        for (int c = 0; c < 3; ++c) {
            const float* __restrict__ src = pts + (b * 3 + c) * NN;
            const float sub = ctr[(b * 3 + c) * MM + m0 + lane];
            float v[4];
            #pragma unroll
            for (int j = 0; j < 4; ++j) v[j] = __ldg(src + idx4[j]);
            #pragma unroll
            for (int j = 0; j < 4; ++j)
                out[(size_t)((b * 35 + c) * KK + w * 4 + j) * MM + m0 + lane] =
                    __fadd_rn(v[j], -sub);
        }

        // Restore g_cellcur = 0 (BB*NC = 20000 counters) for the next call.
        // 256 cleanup blocks x 79 contiguous counters each, disjoint.
        const int cb = (b << 7) + blockIdx.x;    // 0..255
        if (tid < 79) {
            const int ci = cb * 79 + tid;
            if (ci < BB * NC) g_cellcur[ci] = 0;
        }
    }
}

extern "C" void kernel_launch(void* const* d_in, const int* in_sizes, int n_in,
                              void* d_out, int out_size)
{
    const float* pts  = (const float*)d_in[0];   // [B][3][N]
    const float* ctr  = (const float*)d_in[1];   // [B][3][M]
    const float* feat = (const float*)d_in[2];   // [B][C][N]
    float* out = (float*)d_out;

    count_transpose_kernel<<<(BB * NN) / 256 + BB * (NN / 32), 256>>>(pts, feat);
    prefix_kernel<<<BB, 1024>>>();
    scatter_kernel<<<(BB * NN) / (256 * 2), 256>>>(pts);
    query_kernel<<<BB * MM / QW, 256>>>(ctr);

    {
        dim3 grid(MM / 32, 5, BB);
        group_kernel<<<grid, 256>>>(pts, ctr, out);
    }
}